// round 1
// baseline (speedup 1.0000x reference)
#include <cuda_runtime.h>
#include <cstdint>

#define N_NODE 100000        // N_USER == N_ITEM == 100000
#define NEDGE  1000000
#define C      128
#define CC     (C * C)
#define NC     ((size_t)N_NODE * C)

// ---------------- device scratch (allowed: __device__ globals) ----------------
__device__ __align__(16) float g_xu[NC];          // user features after layer 0
__device__ __align__(16) float g_xi[NC];          // item features after layer 0
__device__ __align__(16) float g_agg[3][NC];      // 0: ui->item, 1: iu->user, 2: uu->user
__device__ __align__(16) int   g_cnt[3 * N_NODE];
__device__ __align__(16) float g_inv[3 * N_NODE];

// ---------------- tiny utility kernels ----------------
__global__ void zero_k(float4* __restrict__ p, long n4) {
    long i = (long)blockIdx.x * blockDim.x + threadIdx.x;
    long st = (long)gridDim.x * blockDim.x;
    float4 z = make_float4(0.f, 0.f, 0.f, 0.f);
    for (; i < n4; i += st) p[i] = z;
}

__global__ void count_k(const int* __restrict__ dst, int* __restrict__ cnt, int E) {
    int i = blockIdx.x * blockDim.x + threadIdx.x;
    int st = gridDim.x * blockDim.x;
    for (; i < E; i += st) atomicAdd(cnt + dst[i], 1);
}

__global__ void inv_k(const int* __restrict__ cnt, float* __restrict__ inv, int n) {
    int i = blockIdx.x * blockDim.x + threadIdx.x;
    if (i < n) {
        int c = cnt[i];
        inv[i] = 1.0f / (float)(c > 1 ? c : 1);
    }
}

// ---------------- edge scatter: one warp per edge, vector reduction ----------------
__global__ void __launch_bounds__(256) scatter_k(
    const float* __restrict__ x, const int* __restrict__ ei,
    float* __restrict__ agg, int E)
{
    int lane = threadIdx.x & 31;
    int w = (blockIdx.x * blockDim.x + threadIdx.x) >> 5;
    int nw = (gridDim.x * blockDim.x) >> 5;
    for (int e = w; e < E; e += nw) {
        int s = __ldg(ei + e);           // src node
        int d = __ldg(ei + E + e);       // dst node
        float4 v = __ldg((const float4*)(x + (size_t)s * C) + lane);
        float* p = agg + (size_t)d * C + (size_t)lane * 4;
        asm volatile("red.global.add.v4.f32 [%0], {%1,%2,%3,%4};"
                     :: "l"(p), "f"(v.x), "f"(v.y), "f"(v.z), "f"(v.w)
                     : "memory");
    }
}

// ---------------- fused multi-term GEMM + bias + LayerNorm + ReLU ----------------
// out[n,:] = relu(LN( sum_t (A_t[n,:] * scale_t(n)) @ W_t  + bias0 + bias1 ))
// Block: 256 threads, BM=64 nodes. Warp w owns nodes w*8..w*8+7; lane owns cols lane*4..+3.
template <int NTERMS>
__global__ void __launch_bounds__(256) gemm_ln_relu(
    const float* __restrict__ A0, const float* __restrict__ inv0, const float* __restrict__ W0,
    const float* __restrict__ A1, const float* __restrict__ inv1, const float* __restrict__ W1,
    const float* __restrict__ A2, const float* __restrict__ inv2, const float* __restrict__ W2,
    const float* __restrict__ A3, const float* __restrict__ inv3, const float* __restrict__ W3,
    const float* __restrict__ bias0, const float* __restrict__ bias1,
    const float* __restrict__ lnw, const float* __restrict__ lnb,
    float* __restrict__ out, int N)
{
    extern __shared__ float smem[];
    float* sA = smem;              // 64 x 128
    float* sW = smem + 64 * C;     // 128 x 128
    float4* sA4 = (float4*)sA;
    float4* sW4 = (float4*)sW;

    const int t = threadIdx.x;
    const int warp = t >> 5;
    const int lane = t & 31;
    const int nodeBase = blockIdx.x * 64;

    const float* As[4]   = {A0, A1, A2, A3};
    const float* invs[4] = {inv0, inv1, inv2, inv3};
    const float* Ws[4]   = {W0, W1, W2, W3};

    float acc[8][4];
#pragma unroll
    for (int j = 0; j < 8; ++j) {
        acc[j][0] = 0.f; acc[j][1] = 0.f; acc[j][2] = 0.f; acc[j][3] = 0.f;
    }

#pragma unroll 1
    for (int term = 0; term < NTERMS; ++term) {
        const float* A = As[term];
        const float* inv = invs[term];
        const float4* W4 = (const float4*)Ws[term];

        __syncthreads();   // protect previous iteration's smem reads
        // stage W: 128x128 f32 = 4096 float4, 16 per thread
#pragma unroll
        for (int i = 0; i < 16; ++i) sW4[t + i * 256] = W4[t + i * 256];
        // stage A tile (with mean scaling): 64x128 f32 = 2048 float4, 8 per thread
#pragma unroll
        for (int i = 0; i < 8; ++i) {
            int f = t + i * 256;
            int r = f >> 5;                // row within tile (32 float4 per row)
            int node = nodeBase + r;
            float4 v = make_float4(0.f, 0.f, 0.f, 0.f);
            if (node < N) {
                v = __ldg((const float4*)(A + (size_t)node * C) + (f & 31));
                float s = inv ? __ldg(inv + node) : 1.0f;
                v.x *= s; v.y *= s; v.z *= s; v.w *= s;
            }
            sA4[f] = v;
        }
        __syncthreads();

#pragma unroll 4
        for (int k = 0; k < C; ++k) {
            float4 w = sW4[k * 32 + lane];
#pragma unroll
            for (int j = 0; j < 8; ++j) {
                float a = sA[(warp * 8 + j) * C + k];
                acc[j][0] += a * w.x;
                acc[j][1] += a * w.y;
                acc[j][2] += a * w.z;
                acc[j][3] += a * w.w;
            }
        }
    }

    // epilogue: bias + LayerNorm + ReLU
    float4 bv = make_float4(0.f, 0.f, 0.f, 0.f);
    if (bias0) {
        float4 b = __ldg((const float4*)bias0 + lane);
        bv.x += b.x; bv.y += b.y; bv.z += b.z; bv.w += b.w;
    }
    if (bias1) {
        float4 b = __ldg((const float4*)bias1 + lane);
        bv.x += b.x; bv.y += b.y; bv.z += b.z; bv.w += b.w;
    }
    float4 gw = __ldg((const float4*)lnw + lane);
    float4 gb = __ldg((const float4*)lnb + lane);

#pragma unroll 1
    for (int j = 0; j < 8; ++j) {
        int node = nodeBase + warp * 8 + j;
        if (node >= N) break;    // uniform across warp
        float v0 = acc[j][0] + bv.x;
        float v1 = acc[j][1] + bv.y;
        float v2 = acc[j][2] + bv.z;
        float v3 = acc[j][3] + bv.w;
        float s  = v0 + v1 + v2 + v3;
        float sq = v0 * v0 + v1 * v1 + v2 * v2 + v3 * v3;
#pragma unroll
        for (int o = 16; o > 0; o >>= 1) {
            s  += __shfl_xor_sync(0xffffffffu, s, o);
            sq += __shfl_xor_sync(0xffffffffu, sq, o);
        }
        float mu  = s * (1.0f / C);
        float var = sq * (1.0f / C) - mu * mu;
        float r   = rsqrtf(var + 1e-5f);
        float4 o4;
        o4.x = fmaxf((v0 - mu) * r * gw.x + gb.x, 0.f);
        o4.y = fmaxf((v1 - mu) * r * gw.y + gb.y, 0.f);
        o4.z = fmaxf((v2 - mu) * r * gw.z + gb.z, 0.f);
        o4.w = fmaxf((v3 - mu) * r * gw.w + gb.w, 0.f);
        *((float4*)(out + (size_t)node * C) + lane) = o4;
    }
}

// ---------------- host launcher ----------------
extern "C" void kernel_launch(void* const* d_in, const int* in_sizes, int n_in,
                              void* d_out, int out_size)
{
    const float* x_user = (const float*)d_in[0];
    const float* x_item = (const float*)d_in[1];
    const int*   ei_ui  = (const int*)d_in[2];
    const int*   ei_iu  = (const int*)d_in[3];
    const int*   ei_uu  = (const int*)d_in[4];
    const float* Wl     = (const float*)d_in[5];
    const float* bl     = (const float*)d_in[6];
    const float* Wr     = (const float*)d_in[7];
    const float* ln_w   = (const float*)d_in[8];
    const float* ln_b   = (const float*)d_in[9];
    float* out = (float*)d_out;

    void *pxu_, *pxi_, *pagg_, *pcnt_, *pinv_;
    cudaGetSymbolAddress(&pxu_, g_xu);
    cudaGetSymbolAddress(&pxi_, g_xi);
    cudaGetSymbolAddress(&pagg_, g_agg);
    cudaGetSymbolAddress(&pcnt_, g_cnt);
    cudaGetSymbolAddress(&pinv_, g_inv);
    float* pxu  = (float*)pxu_;
    float* pxi  = (float*)pxi_;
    float* pagg = (float*)pagg_;
    int*   pcnt = (int*)pcnt_;
    float* pinv = (float*)pinv_;

    const int smem_bytes = (64 * C + C * C) * (int)sizeof(float);   // 96 KB
    cudaFuncSetAttribute((const void*)gemm_ln_relu<2>,
                         cudaFuncAttributeMaxDynamicSharedMemorySize, smem_bytes);
    cudaFuncSetAttribute((const void*)gemm_ln_relu<4>,
                         cudaFuncAttributeMaxDynamicSharedMemorySize, smem_bytes);

    // degree counts (edges identical across layers -> compute once)
    zero_k<<<256, 256>>>((float4*)pcnt, (long)(3 * N_NODE) / 4);
    count_k<<<2048, 256>>>(ei_ui + NEDGE, pcnt + 0 * N_NODE, NEDGE);
    count_k<<<2048, 256>>>(ei_iu + NEDGE, pcnt + 1 * N_NODE, NEDGE);
    count_k<<<2048, 256>>>(ei_uu + NEDGE, pcnt + 2 * N_NODE, NEDGE);
    inv_k<<<(3 * N_NODE + 255) / 256, 256>>>(pcnt, pinv, 3 * N_NODE);

    const int gemm_blocks = (N_NODE + 63) / 64;

    for (int l = 0; l < 2; ++l) {
        const float* xu_src = (l == 0) ? x_user : pxu;
        const float* xi_src = (l == 0) ? x_item : pxi;
        float* outu = (l == 0) ? pxu : out;
        float* outi = (l == 0) ? pxi : out + NC;

        // zero all three agg buffers
        zero_k<<<4096, 256>>>((float4*)pagg, (long)(3 * NC) / 4);

        // scatter per edge type
        scatter_k<<<8192, 256>>>(xu_src, ei_ui, pagg + 0 * NC, NEDGE);  // user->item
        scatter_k<<<8192, 256>>>(xi_src, ei_iu, pagg + 1 * NC, NEDGE);  // item->user
        scatter_k<<<8192, 256>>>(xu_src, ei_uu, pagg + 2 * NC, NEDGE);  // user->user

        // item output: mean_ui @ Wl[l,0] + bl[l,0] + xi @ Wr[l,0] -> LN(l,item=1) -> ReLU
        gemm_ln_relu<2><<<gemm_blocks, 256, smem_bytes>>>(
            pagg + 0 * NC, pinv + 0 * N_NODE, Wl + (size_t)(l * 3 + 0) * CC,
            xi_src,        nullptr,           Wr + (size_t)(l * 3 + 0) * CC,
            nullptr, nullptr, nullptr,
            nullptr, nullptr, nullptr,
            bl + (size_t)(l * 3 + 0) * C, nullptr,
            ln_w + (size_t)(l * 2 + 1) * C, ln_b + (size_t)(l * 2 + 1) * C,
            outi, N_NODE);

        // user output: mean_iu@Wl[l,1] + bl[l,1] + xu@Wr[l,1]
        //            + mean_uu@Wl[l,2] + bl[l,2] + xu@Wr[l,2] -> LN(l,user=0) -> ReLU
        gemm_ln_relu<4><<<gemm_blocks, 256, smem_bytes>>>(
            pagg + 1 * NC, pinv + 1 * N_NODE, Wl + (size_t)(l * 3 + 1) * CC,
            xu_src,        nullptr,           Wr + (size_t)(l * 3 + 1) * CC,
            pagg + 2 * NC, pinv + 2 * N_NODE, Wl + (size_t)(l * 3 + 2) * CC,
            xu_src,        nullptr,           Wr + (size_t)(l * 3 + 2) * CC,
            bl + (size_t)(l * 3 + 1) * C, bl + (size_t)(l * 3 + 2) * C,
            ln_w + (size_t)(l * 2 + 0) * C, ln_b + (size_t)(l * 2 + 0) * C,
            outu, N_NODE);
    }
}

// round 2
// speedup vs baseline: 1.0102x; 1.0102x over previous
#include <cuda_runtime.h>
#include <cstdint>

#define N_NODE 100000        // N_USER == N_ITEM == 100000
#define NEDGE  1000000
#define C      128
#define CC     (C * C)
#define NC     ((size_t)N_NODE * C)

// ---------------- device scratch (allowed: __device__ globals) ----------------
__device__ __align__(16) float g_xu[NC];          // user features after layer 0
__device__ __align__(16) float g_xi[NC];          // item features after layer 0
__device__ __align__(16) float g_agg[3][NC];      // 0: ui->item, 1: iu->user, 2: uu->user
__device__ __align__(16) int   g_cnt[3 * N_NODE];
__device__ __align__(16) float g_inv[3 * N_NODE];

// ---------------- tiny utility kernels ----------------
__global__ void zero_k(float4* __restrict__ p, long n4) {
    long i = (long)blockIdx.x * blockDim.x + threadIdx.x;
    long st = (long)gridDim.x * blockDim.x;
    float4 z = make_float4(0.f, 0.f, 0.f, 0.f);
    for (; i < n4; i += st) p[i] = z;
}

__global__ void count_k(const int* __restrict__ dst, int* __restrict__ cnt, int E) {
    int i = blockIdx.x * blockDim.x + threadIdx.x;
    int st = gridDim.x * blockDim.x;
    for (; i < E; i += st) atomicAdd(cnt + dst[i], 1);
}

__global__ void inv_k(const int* __restrict__ cnt, float* __restrict__ inv, int n) {
    int i = blockIdx.x * blockDim.x + threadIdx.x;
    if (i < n) {
        int c = cnt[i];
        inv[i] = 1.0f / (float)(c > 1 ? c : 1);
    }
}

// ---------------- edge scatter: one warp per edge, vector reduction ----------------
__global__ void __launch_bounds__(256) scatter_k(
    const float* __restrict__ x, const int* __restrict__ ei,
    float* __restrict__ agg, int E)
{
    int lane = threadIdx.x & 31;
    int w = (blockIdx.x * blockDim.x + threadIdx.x) >> 5;
    int nw = (gridDim.x * blockDim.x) >> 5;
    for (int e = w; e < E; e += nw) {
        int s = __ldg(ei + e);           // src node
        int d = __ldg(ei + E + e);       // dst node
        float4 v = __ldg((const float4*)(x + (size_t)s * C) + lane);
        float* p = agg + (size_t)d * C + (size_t)lane * 4;
        asm volatile("red.global.add.v4.f32 [%0], {%1,%2,%3,%4};"
                     :: "l"(p), "f"(v.x), "f"(v.y), "f"(v.z), "f"(v.w)
                     : "memory");
    }
}

// ---------------- fused multi-term GEMM + bias + LayerNorm + ReLU ----------------
// out[n,:] = relu(LN( sum_t (A_t[n,:] * scale_t(n)) @ W_t  + bias0 + bias1 ))
// Block: 256 threads, BM=64 nodes. Warp w owns nodes w*8..w*8+7; lane owns cols lane*4..+3.
template <int NTERMS>
__global__ void __launch_bounds__(256) gemm_ln_relu(
    const float* __restrict__ A0, const float* __restrict__ inv0, const float* __restrict__ W0,
    const float* __restrict__ A1, const float* __restrict__ inv1, const float* __restrict__ W1,
    const float* __restrict__ A2, const float* __restrict__ inv2, const float* __restrict__ W2,
    const float* __restrict__ A3, const float* __restrict__ inv3, const float* __restrict__ W3,
    const float* __restrict__ bias0, const float* __restrict__ bias1,
    const float* __restrict__ lnw, const float* __restrict__ lnb,
    float* __restrict__ out, int N)
{
    extern __shared__ float smem[];
    float* sA = smem;              // 64 x 128
    float* sW = smem + 64 * C;     // 128 x 128
    float4* sA4 = (float4*)sA;
    float4* sW4 = (float4*)sW;

    const int t = threadIdx.x;
    const int warp = t >> 5;
    const int lane = t & 31;
    const int nodeBase = blockIdx.x * 64;

    const float* As[4]   = {A0, A1, A2, A3};
    const float* invs[4] = {inv0, inv1, inv2, inv3};
    const float* Ws[4]   = {W0, W1, W2, W3};

    float acc[8][4];
#pragma unroll
    for (int j = 0; j < 8; ++j) {
        acc[j][0] = 0.f; acc[j][1] = 0.f; acc[j][2] = 0.f; acc[j][3] = 0.f;
    }

#pragma unroll 1
    for (int term = 0; term < NTERMS; ++term) {
        const float* A = As[term];
        const float* inv = invs[term];
        const float4* W4 = (const float4*)Ws[term];

        __syncthreads();   // protect previous iteration's smem reads
        // stage W: 128x128 f32 = 4096 float4, 16 per thread
#pragma unroll
        for (int i = 0; i < 16; ++i) sW4[t + i * 256] = W4[t + i * 256];
        // stage A tile (with mean scaling): 64x128 f32 = 2048 float4, 8 per thread
#pragma unroll
        for (int i = 0; i < 8; ++i) {
            int f = t + i * 256;
            int r = f >> 5;                // row within tile (32 float4 per row)
            int node = nodeBase + r;
            float4 v = make_float4(0.f, 0.f, 0.f, 0.f);
            if (node < N) {
                v = __ldg((const float4*)(A + (size_t)node * C) + (f & 31));
                float s = inv ? __ldg(inv + node) : 1.0f;
                v.x *= s; v.y *= s; v.z *= s; v.w *= s;
            }
            sA4[f] = v;
        }
        __syncthreads();

#pragma unroll 4
        for (int k = 0; k < C; ++k) {
            float4 w = sW4[k * 32 + lane];
#pragma unroll
            for (int j = 0; j < 8; ++j) {
                float a = sA[(warp * 8 + j) * C + k];
                acc[j][0] += a * w.x;
                acc[j][1] += a * w.y;
                acc[j][2] += a * w.z;
                acc[j][3] += a * w.w;
            }
        }
    }

    // epilogue: bias + LayerNorm + ReLU
    float4 bv = make_float4(0.f, 0.f, 0.f, 0.f);
    if (bias0) {
        float4 b = __ldg((const float4*)bias0 + lane);
        bv.x += b.x; bv.y += b.y; bv.z += b.z; bv.w += b.w;
    }
    if (bias1) {
        float4 b = __ldg((const float4*)bias1 + lane);
        bv.x += b.x; bv.y += b.y; bv.z += b.z; bv.w += b.w;
    }
    float4 gw = __ldg((const float4*)lnw + lane);
    float4 gb = __ldg((const float4*)lnb + lane);

#pragma unroll 1
    for (int j = 0; j < 8; ++j) {
        int node = nodeBase + warp * 8 + j;
        if (node >= N) break;    // uniform across warp
        float v0 = acc[j][0] + bv.x;
        float v1 = acc[j][1] + bv.y;
        float v2 = acc[j][2] + bv.z;
        float v3 = acc[j][3] + bv.w;
        float s  = v0 + v1 + v2 + v3;
        float sq = v0 * v0 + v1 * v1 + v2 * v2 + v3 * v3;
#pragma unroll
        for (int o = 16; o > 0; o >>= 1) {
            s  += __shfl_xor_sync(0xffffffffu, s, o);
            sq += __shfl_xor_sync(0xffffffffu, sq, o);
        }
        float mu  = s * (1.0f / C);
        float var = sq * (1.0f / C) - mu * mu;
        float r   = rsqrtf(var + 1e-5f);
        float4 o4;
        o4.x = fmaxf((v0 - mu) * r * gw.x + gb.x, 0.f);
        o4.y = fmaxf((v1 - mu) * r * gw.y + gb.y, 0.f);
        o4.z = fmaxf((v2 - mu) * r * gw.z + gb.z, 0.f);
        o4.w = fmaxf((v3 - mu) * r * gw.w + gb.w, 0.f);
        *((float4*)(out + (size_t)node * C) + lane) = o4;
    }
}

// ---------------- host launcher ----------------
extern "C" void kernel_launch(void* const* d_in, const int* in_sizes, int n_in,
                              void* d_out, int out_size)
{
    const float* x_user = (const float*)d_in[0];
    const float* x_item = (const float*)d_in[1];
    const int*   ei_ui  = (const int*)d_in[2];
    const int*   ei_iu  = (const int*)d_in[3];
    const int*   ei_uu  = (const int*)d_in[4];
    const float* Wl     = (const float*)d_in[5];
    const float* bl     = (const float*)d_in[6];
    const float* Wr     = (const float*)d_in[7];
    const float* ln_w   = (const float*)d_in[8];
    const float* ln_b   = (const float*)d_in[9];
    float* out = (float*)d_out;

    void *pxu_, *pxi_, *pagg_, *pcnt_, *pinv_;
    cudaGetSymbolAddress(&pxu_, g_xu);
    cudaGetSymbolAddress(&pxi_, g_xi);
    cudaGetSymbolAddress(&pagg_, g_agg);
    cudaGetSymbolAddress(&pcnt_, g_cnt);
    cudaGetSymbolAddress(&pinv_, g_inv);
    float* pxu  = (float*)pxu_;
    float* pxi  = (float*)pxi_;
    float* pagg = (float*)pagg_;
    int*   pcnt = (int*)pcnt_;
    float* pinv = (float*)pinv_;

    const int smem_bytes = (64 * C + C * C) * (int)sizeof(float);   // 96 KB
    cudaFuncSetAttribute((const void*)gemm_ln_relu<2>,
                         cudaFuncAttributeMaxDynamicSharedMemorySize, smem_bytes);
    cudaFuncSetAttribute((const void*)gemm_ln_relu<4>,
                         cudaFuncAttributeMaxDynamicSharedMemorySize, smem_bytes);

    // degree counts (edges identical across layers -> compute once)
    zero_k<<<256, 256>>>((float4*)pcnt, (long)(3 * N_NODE) / 4);
    count_k<<<2048, 256>>>(ei_ui + NEDGE, pcnt + 0 * N_NODE, NEDGE);
    count_k<<<2048, 256>>>(ei_iu + NEDGE, pcnt + 1 * N_NODE, NEDGE);
    count_k<<<2048, 256>>>(ei_uu + NEDGE, pcnt + 2 * N_NODE, NEDGE);
    inv_k<<<(3 * N_NODE + 255) / 256, 256>>>(pcnt, pinv, 3 * N_NODE);

    const int gemm_blocks = (N_NODE + 63) / 64;

    for (int l = 0; l < 2; ++l) {
        const float* xu_src = (l == 0) ? x_user : pxu;
        const float* xi_src = (l == 0) ? x_item : pxi;
        float* outu = (l == 0) ? pxu : out;
        float* outi = (l == 0) ? pxi : out + NC;

        // zero all three agg buffers
        zero_k<<<4096, 256>>>((float4*)pagg, (long)(3 * NC) / 4);

        // scatter per edge type
        scatter_k<<<8192, 256>>>(xu_src, ei_ui, pagg + 0 * NC, NEDGE);  // user->item
        scatter_k<<<8192, 256>>>(xi_src, ei_iu, pagg + 1 * NC, NEDGE);  // item->user
        scatter_k<<<8192, 256>>>(xu_src, ei_uu, pagg + 2 * NC, NEDGE);  // user->user

        // item output: mean_ui @ Wl[l,0] + bl[l,0] + xi @ Wr[l,0] -> LN(l,item=1) -> ReLU
        gemm_ln_relu<2><<<gemm_blocks, 256, smem_bytes>>>(
            pagg + 0 * NC, pinv + 0 * N_NODE, Wl + (size_t)(l * 3 + 0) * CC,
            xi_src,        nullptr,           Wr + (size_t)(l * 3 + 0) * CC,
            nullptr, nullptr, nullptr,
            nullptr, nullptr, nullptr,
            bl + (size_t)(l * 3 + 0) * C, nullptr,
            ln_w + (size_t)(l * 2 + 1) * C, ln_b + (size_t)(l * 2 + 1) * C,
            outi, N_NODE);

        // user output: mean_iu@Wl[l,1] + bl[l,1] + xu@Wr[l,1]
        //            + mean_uu@Wl[l,2] + bl[l,2] + xu@Wr[l,2] -> LN(l,user=0) -> ReLU
        gemm_ln_relu<4><<<gemm_blocks, 256, smem_bytes>>>(
            pagg + 1 * NC, pinv + 1 * N_NODE, Wl + (size_t)(l * 3 + 1) * CC,
            xu_src,        nullptr,           Wr + (size_t)(l * 3 + 1) * CC,
            pagg + 2 * NC, pinv + 2 * N_NODE, Wl + (size_t)(l * 3 + 2) * CC,
            xu_src,        nullptr,           Wr + (size_t)(l * 3 + 2) * CC,
            bl + (size_t)(l * 3 + 1) * C, bl + (size_t)(l * 3 + 2) * C,
            ln_w + (size_t)(l * 2 + 0) * C, ln_b + (size_t)(l * 2 + 0) * C,
            outu, N_NODE);
    }
}

// round 3
// speedup vs baseline: 1.0107x; 1.0004x over previous
#include <cuda_runtime.h>
#include <cstdint>

#define N_NODE 100000        // N_USER == N_ITEM == 100000
#define NEDGE  1000000
#define C      128
#define CC     (C * C)
#define NC     ((size_t)N_NODE * C)

// ---------------- device scratch (allowed: __device__ globals) ----------------
__device__ __align__(16) float g_xu[NC];          // user features after layer 0
__device__ __align__(16) float g_xi[NC];          // item features after layer 0
__device__ __align__(16) float g_agg[3][NC];      // 0: ui->item, 1: iu->user, 2: uu->user
__device__ __align__(16) int   g_cnt[3 * N_NODE];
__device__ __align__(16) float g_inv[3 * N_NODE];

// ---------------- tiny utility kernels ----------------
__global__ void zero_k(float4* __restrict__ p, long n4) {
    long i = (long)blockIdx.x * blockDim.x + threadIdx.x;
    long st = (long)gridDim.x * blockDim.x;
    float4 z = make_float4(0.f, 0.f, 0.f, 0.f);
    for (; i < n4; i += st) p[i] = z;
}

__global__ void count_k(const int* __restrict__ dst, int* __restrict__ cnt, int E) {
    int i = blockIdx.x * blockDim.x + threadIdx.x;
    int st = gridDim.x * blockDim.x;
    for (; i < E; i += st) atomicAdd(cnt + dst[i], 1);
}

__global__ void inv_k(const int* __restrict__ cnt, float* __restrict__ inv, int n) {
    int i = blockIdx.x * blockDim.x + threadIdx.x;
    if (i < n) {
        int c = cnt[i];
        inv[i] = 1.0f / (float)(c > 1 ? c : 1);
    }
}

// ---------------- edge scatter: one warp per edge, vector reduction ----------------
__global__ void __launch_bounds__(256) scatter_k(
    const float* __restrict__ x, const int* __restrict__ ei,
    float* __restrict__ agg, int E)
{
    int lane = threadIdx.x & 31;
    int w = (blockIdx.x * blockDim.x + threadIdx.x) >> 5;
    int nw = (gridDim.x * blockDim.x) >> 5;
    for (int e = w; e < E; e += nw) {
        int s = __ldg(ei + e);           // src node
        int d = __ldg(ei + E + e);       // dst node
        float4 v = __ldg((const float4*)(x + (size_t)s * C) + lane);
        float* p = agg + (size_t)d * C + (size_t)lane * 4;
        asm volatile("red.global.add.v4.f32 [%0], {%1,%2,%3,%4};"
                     :: "l"(p), "f"(v.x), "f"(v.y), "f"(v.z), "f"(v.w)
                     : "memory");
    }
}

// ---------------- fused multi-term GEMM + bias + LayerNorm + ReLU ----------------
// out[n,:] = relu(LN( sum_t (A_t[n,:] * scale_t(n)) @ W_t  + bias0 + bias1 ))
// Block: 256 threads, BM=64 nodes. Warp w owns nodes w*8..w*8+7; lane owns cols lane*4..+3.
template <int NTERMS>
__global__ void __launch_bounds__(256) gemm_ln_relu(
    const float* __restrict__ A0, const float* __restrict__ inv0, const float* __restrict__ W0,
    const float* __restrict__ A1, const float* __restrict__ inv1, const float* __restrict__ W1,
    const float* __restrict__ A2, const float* __restrict__ inv2, const float* __restrict__ W2,
    const float* __restrict__ A3, const float* __restrict__ inv3, const float* __restrict__ W3,
    const float* __restrict__ bias0, const float* __restrict__ bias1,
    const float* __restrict__ lnw, const float* __restrict__ lnb,
    float* __restrict__ out, int N)
{
    extern __shared__ float smem[];
    float* sA = smem;              // 64 x 128
    float* sW = smem + 64 * C;     // 128 x 128
    float4* sA4 = (float4*)sA;
    float4* sW4 = (float4*)sW;

    const int t = threadIdx.x;
    const int warp = t >> 5;
    const int lane = t & 31;
    const int nodeBase = blockIdx.x * 64;

    const float* As[4]   = {A0, A1, A2, A3};
    const float* invs[4] = {inv0, inv1, inv2, inv3};
    const float* Ws[4]   = {W0, W1, W2, W3};

    float acc[8][4];
#pragma unroll
    for (int j = 0; j < 8; ++j) {
        acc[j][0] = 0.f; acc[j][1] = 0.f; acc[j][2] = 0.f; acc[j][3] = 0.f;
    }

#pragma unroll 1
    for (int term = 0; term < NTERMS; ++term) {
        const float* A = As[term];
        const float* inv = invs[term];
        const float4* W4 = (const float4*)Ws[term];

        __syncthreads();   // protect previous iteration's smem reads
        // stage W: 128x128 f32 = 4096 float4, 16 per thread
#pragma unroll
        for (int i = 0; i < 16; ++i) sW4[t + i * 256] = W4[t + i * 256];
        // stage A tile (with mean scaling): 64x128 f32 = 2048 float4, 8 per thread
#pragma unroll
        for (int i = 0; i < 8; ++i) {
            int f = t + i * 256;
            int r = f >> 5;                // row within tile (32 float4 per row)
            int node = nodeBase + r;
            float4 v = make_float4(0.f, 0.f, 0.f, 0.f);
            if (node < N) {
                v = __ldg((const float4*)(A + (size_t)node * C) + (f & 31));
                float s = inv ? __ldg(inv + node) : 1.0f;
                v.x *= s; v.y *= s; v.z *= s; v.w *= s;
            }
            sA4[f] = v;
        }
        __syncthreads();

#pragma unroll 4
        for (int k = 0; k < C; ++k) {
            float4 w = sW4[k * 32 + lane];
#pragma unroll
            for (int j = 0; j < 8; ++j) {
                float a = sA[(warp * 8 + j) * C + k];
                acc[j][0] += a * w.x;
                acc[j][1] += a * w.y;
                acc[j][2] += a * w.z;
                acc[j][3] += a * w.w;
            }
        }
    }

    // epilogue: bias + LayerNorm + ReLU
    float4 bv = make_float4(0.f, 0.f, 0.f, 0.f);
    if (bias0) {
        float4 b = __ldg((const float4*)bias0 + lane);
        bv.x += b.x; bv.y += b.y; bv.z += b.z; bv.w += b.w;
    }
    if (bias1) {
        float4 b = __ldg((const float4*)bias1 + lane);
        bv.x += b.x; bv.y += b.y; bv.z += b.z; bv.w += b.w;
    }
    float4 gw = __ldg((const float4*)lnw + lane);
    float4 gb = __ldg((const float4*)lnb + lane);

#pragma unroll 1
    for (int j = 0; j < 8; ++j) {
        int node = nodeBase + warp * 8 + j;
        if (node >= N) break;    // uniform across warp
        float v0 = acc[j][0] + bv.x;
        float v1 = acc[j][1] + bv.y;
        float v2 = acc[j][2] + bv.z;
        float v3 = acc[j][3] + bv.w;
        float s  = v0 + v1 + v2 + v3;
        float sq = v0 * v0 + v1 * v1 + v2 * v2 + v3 * v3;
#pragma unroll
        for (int o = 16; o > 0; o >>= 1) {
            s  += __shfl_xor_sync(0xffffffffu, s, o);
            sq += __shfl_xor_sync(0xffffffffu, sq, o);
        }
        float mu  = s * (1.0f / C);
        float var = sq * (1.0f / C) - mu * mu;
        float r   = rsqrtf(var + 1e-5f);
        float4 o4;
        o4.x = fmaxf((v0 - mu) * r * gw.x + gb.x, 0.f);
        o4.y = fmaxf((v1 - mu) * r * gw.y + gb.y, 0.f);
        o4.z = fmaxf((v2 - mu) * r * gw.z + gb.z, 0.f);
        o4.w = fmaxf((v3 - mu) * r * gw.w + gb.w, 0.f);
        *((float4*)(out + (size_t)node * C) + lane) = o4;
    }
}

// ---------------- host launcher ----------------
extern "C" void kernel_launch(void* const* d_in, const int* in_sizes, int n_in,
                              void* d_out, int out_size)
{
    const float* x_user = (const float*)d_in[0];
    const float* x_item = (const float*)d_in[1];
    const int*   ei_ui  = (const int*)d_in[2];
    const int*   ei_iu  = (const int*)d_in[3];
    const int*   ei_uu  = (const int*)d_in[4];
    const float* Wl     = (const float*)d_in[5];
    const float* bl     = (const float*)d_in[6];
    const float* Wr     = (const float*)d_in[7];
    const float* ln_w   = (const float*)d_in[8];
    const float* ln_b   = (const float*)d_in[9];
    float* out = (float*)d_out;

    void *pxu_, *pxi_, *pagg_, *pcnt_, *pinv_;
    cudaGetSymbolAddress(&pxu_, g_xu);
    cudaGetSymbolAddress(&pxi_, g_xi);
    cudaGetSymbolAddress(&pagg_, g_agg);
    cudaGetSymbolAddress(&pcnt_, g_cnt);
    cudaGetSymbolAddress(&pinv_, g_inv);
    float* pxu  = (float*)pxu_;
    float* pxi  = (float*)pxi_;
    float* pagg = (float*)pagg_;
    int*   pcnt = (int*)pcnt_;
    float* pinv = (float*)pinv_;

    const int smem_bytes = (64 * C + C * C) * (int)sizeof(float);   // 96 KB
    cudaFuncSetAttribute((const void*)gemm_ln_relu<2>,
                         cudaFuncAttributeMaxDynamicSharedMemorySize, smem_bytes);
    cudaFuncSetAttribute((const void*)gemm_ln_relu<4>,
                         cudaFuncAttributeMaxDynamicSharedMemorySize, smem_bytes);

    // degree counts (edges identical across layers -> compute once)
    zero_k<<<256, 256>>>((float4*)pcnt, (long)(3 * N_NODE) / 4);
    count_k<<<2048, 256>>>(ei_ui + NEDGE, pcnt + 0 * N_NODE, NEDGE);
    count_k<<<2048, 256>>>(ei_iu + NEDGE, pcnt + 1 * N_NODE, NEDGE);
    count_k<<<2048, 256>>>(ei_uu + NEDGE, pcnt + 2 * N_NODE, NEDGE);
    inv_k<<<(3 * N_NODE + 255) / 256, 256>>>(pcnt, pinv, 3 * N_NODE);

    const int gemm_blocks = (N_NODE + 63) / 64;

    for (int l = 0; l < 2; ++l) {
        const float* xu_src = (l == 0) ? x_user : pxu;
        const float* xi_src = (l == 0) ? x_item : pxi;
        float* outu = (l == 0) ? pxu : out;
        float* outi = (l == 0) ? pxi : out + NC;

        // zero all three agg buffers
        zero_k<<<4096, 256>>>((float4*)pagg, (long)(3 * NC) / 4);

        // scatter per edge type
        scatter_k<<<8192, 256>>>(xu_src, ei_ui, pagg + 0 * NC, NEDGE);  // user->item
        scatter_k<<<8192, 256>>>(xi_src, ei_iu, pagg + 1 * NC, NEDGE);  // item->user
        scatter_k<<<8192, 256>>>(xu_src, ei_uu, pagg + 2 * NC, NEDGE);  // user->user

        // item output: mean_ui @ Wl[l,0] + bl[l,0] + xi @ Wr[l,0] -> LN(l,item=1) -> ReLU
        gemm_ln_relu<2><<<gemm_blocks, 256, smem_bytes>>>(
            pagg + 0 * NC, pinv + 0 * N_NODE, Wl + (size_t)(l * 3 + 0) * CC,
            xi_src,        nullptr,           Wr + (size_t)(l * 3 + 0) * CC,
            nullptr, nullptr, nullptr,
            nullptr, nullptr, nullptr,
            bl + (size_t)(l * 3 + 0) * C, nullptr,
            ln_w + (size_t)(l * 2 + 1) * C, ln_b + (size_t)(l * 2 + 1) * C,
            outi, N_NODE);

        // user output: mean_iu@Wl[l,1] + bl[l,1] + xu@Wr[l,1]
        //            + mean_uu@Wl[l,2] + bl[l,2] + xu@Wr[l,2] -> LN(l,user=0) -> ReLU
        gemm_ln_relu<4><<<gemm_blocks, 256, smem_bytes>>>(
            pagg + 1 * NC, pinv + 1 * N_NODE, Wl + (size_t)(l * 3 + 1) * CC,
            xu_src,        nullptr,           Wr + (size_t)(l * 3 + 1) * CC,
            pagg + 2 * NC, pinv + 2 * N_NODE, Wl + (size_t)(l * 3 + 2) * CC,
            xu_src,        nullptr,           Wr + (size_t)(l * 3 + 2) * CC,
            bl + (size_t)(l * 3 + 1) * C, bl + (size_t)(l * 3 + 2) * C,
            ln_w + (size_t)(l * 2 + 0) * C, ln_b + (size_t)(l * 2 + 0) * C,
            outu, N_NODE);
    }
}